// round 7
// baseline (speedup 1.0000x reference)
#include <cuda_runtime.h>
#include <cuda_fp16.h>
#include <cstdint>

#define NTOK 49
#define CDIM 128
#define NHEAD 4
#define NWIN 64
#define THREADS 512

// ---- persistent prepped buffers (filled by prep kernels each launch) ----
__device__ __align__(16) __half g_qkvw_h[3 * 128 * 136];  // fp16, [j][136], q-scale folded
__device__ __align__(16) __half g_projw_h[128 * 136];     // fp16, [j][136]
__device__ float g_qkvb[512];                             // fp32 biases (q part scaled) ++ proj_b
__device__ float g_bm[64 * 4 * 49 * 56];                  // fused rel-pos-bias + mask (fp32)

// ---- shared memory layout (byte offsets) ----
// xs  : fp16 [64][136]  x tile, later o tile          17408 B
// wt  : fp16 [128][136] staged weight chunk           34816 B
// sc  : fp32 [4][64][60] scores                       61440 B
// P   : fp16 [4][64][72] probabilities                36864 B
// q   : fp16 [4][64][40]                              20480 B
// k   : fp16 [4][64][40]                              20480 B
// vT  : fp16 [4][32][72] (v transposed, d-major)      18432 B
// sb  : fp32 [512] biases                              2048 B
// out-stage fp32 [64][132] overlays q+k (33792 <= 40960)
#define OFF_XS 0
#define OFF_WT 17408
#define OFF_SC 52224
#define OFF_P  113664
#define OFF_Q  150528
#define OFF_K  171008
#define OFF_VT 191488
#define OFF_B  209920
#define SMEM_BYTES 211968

#define XS_STR 136   // halfs
#define Q_STR  40
#define QH_SZ  (64 * Q_STR)    // per-head halfs
#define VT_STR 72
#define VTH_SZ (32 * VT_STR)
#define P_STR  72
#define PH_SZ  (64 * P_STR)
#define SC_STR 60    // floats
#define SCH_SZ (64 * SC_STR)

__device__ __forceinline__ uint32_t ldu32(const __half* p) {
    return *reinterpret_cast<const uint32_t*>(p);
}

__device__ __forceinline__ void mma16(float c[4], const uint32_t a[4], const uint32_t b[2]) {
    asm volatile(
        "mma.sync.aligned.m16n8k16.row.col.f32.f16.f16.f32 "
        "{%0,%1,%2,%3},{%4,%5,%6,%7},{%8,%9},{%0,%1,%2,%3};\n"
        : "+f"(c[0]), "+f"(c[1]), "+f"(c[2]), "+f"(c[3])
        : "r"(a[0]), "r"(a[1]), "r"(a[2]), "r"(a[3]), "r"(b[0]), "r"(b[1]));
}

// ================= prep kernels (once per launch, ~5 us total) =================
__global__ void prep_weights(const float* __restrict__ qkv_w, const float* __restrict__ qkv_b,
                             const float* __restrict__ proj_w, const float* __restrict__ proj_b)
{
    int idx = blockIdx.x * 256 + threadIdx.x;
    const float scale = 0.17677669529663687f;   // 32^-0.5
    if (idx < 49152) {
        int ch = idx >> 14;
        int j  = (idx >> 7) & 127;
        int k  = idx & 127;
        float v = qkv_w[(size_t)(ch * 128 + j) * 128 + k];
        if (ch == 0) v *= scale;
        g_qkvw_h[ch * (128 * 136) + j * 136 + k] = __float2half_rn(v);
    } else if (idx < 65536) {
        int i2 = idx - 49152;
        int j = i2 >> 7, k = i2 & 127;
        g_projw_h[j * 136 + k] = __float2half_rn(proj_w[(size_t)j * 128 + k]);
    } else if (idx < 65536 + 384) {
        int i = idx - 65536;
        float v = qkv_b[i];
        if (i < 128) v *= scale;
        g_qkvb[i] = v;
    } else if (idx < 65536 + 512) {
        int i = idx - 65536;
        g_qkvb[i] = proj_b[i - 384];
    }
}

__global__ void prep_bm(const float* __restrict__ mask, const float* __restrict__ bias_table)
{
    int idx = blockIdx.x * 256 + threadIdx.x;
    if (idx >= 64 * 4 * 49 * 56) return;
    int j = idx % 56;
    int rest = idx / 56;
    int i = rest % 49; rest /= 49;
    int h = rest & 3;
    int w = rest >> 2;
    float v = 0.f;
    if (j < 49) {
        int ih = i / 7, iw = i - 7 * ih;
        int jh = j / 7, jw = j - 7 * jh;
        int ridx = (ih - jh + 6) * 13 + (iw - jw + 6);
        v = bias_table[ridx * 4 + h] + mask[(size_t)(w * 49 + i) * 49 + j];
    }
    g_bm[idx] = v;
}

// ================= main kernel =================
__global__ __launch_bounds__(THREADS, 1)
void window_attn_h(const float* __restrict__ x, float* __restrict__ out)
{
    extern __shared__ char smem[];
    __half* xs = (__half*)(smem + OFF_XS);
    __half* wt = (__half*)(smem + OFF_WT);
    float*  sc = (float*)(smem + OFF_SC);
    __half* Pb = (__half*)(smem + OFF_P);
    __half* qb = (__half*)(smem + OFF_Q);
    __half* kb = (__half*)(smem + OFF_K);
    __half* vt = (__half*)(smem + OFF_VT);
    float*  sb = (float*)(smem + OFF_B);

    const int tid  = threadIdx.x;
    const int wid  = tid >> 5;
    const int lane = tid & 31;
    const int g    = lane >> 2;
    const int t    = lane & 3;
    const int b    = blockIdx.x;

    // ---- Phase 1: x -> fp16 tile [64][136], zero-pad rows 49..63; stage biases ----
    {
        const float4* xb = (const float4*)(x + (size_t)b * (NTOK * CDIM));
        for (int i = tid; i < 64 * 32; i += THREADS) {
            int r = i >> 5, c4 = i & 31;
            float4 v = (r < NTOK) ? xb[r * 32 + c4] : make_float4(0.f, 0.f, 0.f, 0.f);
            __half2* d = (__half2*)(xs + r * XS_STR + c4 * 4);
            d[0] = __floats2half2_rn(v.x, v.y);
            d[1] = __floats2half2_rn(v.z, v.w);
        }
        sb[tid] = g_qkvb[tid];
    }
    __syncthreads();

    // ---- Phase 2: QKV = x @ qkv_w^T + b (q-scale folded), 3 chunks of 128 cols ----
    const int mi = wid & 3;
    const int nq = wid >> 2;
    for (int ch = 0; ch < 3; ch++) {
        {
            const uint4* src = (const uint4*)(g_qkvw_h + ch * (128 * 136));
            uint4* dst = (uint4*)wt;
            for (int i = tid; i < 2176; i += THREADS) dst[i] = src[i];
        }
        __syncthreads();

        const int r0 = mi * 16 + g;
        float acc[4][4];
#pragma unroll
        for (int i = 0; i < 4; i++)
#pragma unroll
            for (int j = 0; j < 4; j++) acc[i][j] = 0.f;

#pragma unroll
        for (int ks = 0; ks < 8; ks++) {
            const int k0 = ks * 16;
            const __half* ar = xs + r0 * XS_STR + k0 + 2 * t;
            uint32_t a[4] = { ldu32(ar), ldu32(ar + 8 * XS_STR),
                              ldu32(ar + 8), ldu32(ar + 8 * XS_STR + 8) };
#pragma unroll
            for (int nt = 0; nt < 4; nt++) {
                const __half* br = wt + (nq * 32 + nt * 8 + g) * XS_STR + k0 + 2 * t;
                uint32_t bb[2] = { ldu32(br), ldu32(br + 8) };
                mma16(acc[nt], a, bb);
            }
        }

        // epilogue -> q / k / vT fp16
        const float* bch = sb + ch * 128;
        const int r0e = mi * 16 + g;
#pragma unroll
        for (int nt = 0; nt < 4; nt++) {
            const int c0 = nq * 32 + nt * 8 + 2 * t;
#pragma unroll
            for (int e = 0; e < 4; e++) {
                const int rr = r0e + ((e >= 2) ? 8 : 0);
                const int cc = c0 + (e & 1);
                const int h = cc >> 5, dd = cc & 31;
                __half hv = __float2half_rn(acc[nt][e] + bch[cc]);
                if (ch == 0)      qb[h * QH_SZ + rr * Q_STR + dd] = hv;
                else if (ch == 1) kb[h * QH_SZ + rr * Q_STR + dd] = hv;
                else              vt[h * VTH_SZ + dd * VT_STR + rr] = hv;
            }
        }
        __syncthreads();
    }

    // ---- Phase 3: scores = q k^T (fp32) + fused(bias+mask) ----
    {
        const int h  = wid >> 2;
        const int m3 = wid & 3;
        const int r0 = m3 * 16 + g;
        const __half* qh = qb + h * QH_SZ;
        const __half* kh = kb + h * QH_SZ;

        float acc[7][4];
#pragma unroll
        for (int i = 0; i < 7; i++)
#pragma unroll
            for (int j = 0; j < 4; j++) acc[i][j] = 0.f;

#pragma unroll
        for (int ks = 0; ks < 2; ks++) {
            const int k0 = ks * 16;
            const __half* ar = qh + r0 * Q_STR + k0 + 2 * t;
            uint32_t a[4] = { ldu32(ar), ldu32(ar + 8 * Q_STR),
                              ldu32(ar + 8), ldu32(ar + 8 * Q_STR + 8) };
#pragma unroll
            for (int nt = 0; nt < 7; nt++) {
                const __half* br = kh + (nt * 8 + g) * Q_STR + k0 + 2 * t;
                uint32_t bb[2] = { ldu32(br), ldu32(br + 8) };
                mma16(acc[nt], a, bb);
            }
        }

        float* at = sc + h * SCH_SZ;
        const float* bmw = g_bm + (size_t)(b & (NWIN - 1)) * (4 * 49 * 56) + h * (49 * 56);
#pragma unroll
        for (int nt = 0; nt < 7; nt++) {
            const int c0 = nt * 8 + 2 * t;
#pragma unroll
            for (int e = 0; e < 4; e++) {
                const int rr = r0 + ((e >= 2) ? 8 : 0);
                const int jj = c0 + (e & 1);
                float v = 0.f;
                if (rr < NTOK && jj < NTOK)
                    v = acc[nt][e] + __ldg(bmw + rr * 56 + jj);
                at[rr * SC_STR + jj] = v;
            }
        }
    }
    __syncthreads();

    // ---- Phase 4: softmax per (h,i) row -> P fp16 [4][64][72]; zero pad rows ----
    if (tid < NHEAD * NTOK) {
        const int h = tid / NTOK;
        const int i = tid - h * NTOK;
        const float* row = sc + h * SCH_SZ + i * SC_STR;
        __half* ph = Pb + h * PH_SZ + i * P_STR;
        float m = row[0];
#pragma unroll
        for (int j = 1; j < NTOK; j++) m = fmaxf(m, row[j]);
        float ssum = 0.f;
#pragma unroll
        for (int j = 0; j < NTOK; j++) ssum += __expf(row[j] - m);
        const float inv = 1.0f / ssum;
#pragma unroll
        for (int j = 0; j < NTOK; j++) ph[j] = __float2half_rn(__expf(row[j] - m) * inv);
#pragma unroll
        for (int j = NTOK; j < 64; j++) ph[j] = __ushort_as_half((unsigned short)0);
    } else {
        int z = tid - NHEAD * NTOK;      // zero P rows 49..63 (4 heads x 15 rows)
        if (z < 60) {
            int h = z / 15, r = NTOK + (z % 15);
            uint4* p4 = (uint4*)(Pb + h * PH_SZ + r * P_STR);
            uint4 zero = make_uint4(0, 0, 0, 0);
#pragma unroll
            for (int q4 = 0; q4 < 8; q4++) p4[q4] = zero;
        }
    }
    __syncthreads();

    // ---- Phase 5: o = P @ V -> xs fp16 [64][136] (cols h*32+d) ----
    {
        const int h  = wid >> 2;
        const int m5 = wid & 3;
        const int r0 = m5 * 16 + g;
        const __half* ph = Pb + h * PH_SZ;
        const __half* vh = vt + h * VTH_SZ;

        float acc[4][4];
#pragma unroll
        for (int i = 0; i < 4; i++)
#pragma unroll
            for (int j = 0; j < 4; j++) acc[i][j] = 0.f;

#pragma unroll
        for (int ks = 0; ks < 4; ks++) {
            const int k0 = ks * 16;
            const __half* ar = ph + r0 * P_STR + k0 + 2 * t;
            uint32_t a[4] = { ldu32(ar), ldu32(ar + 8 * P_STR),
                              ldu32(ar + 8), ldu32(ar + 8 * P_STR + 8) };
#pragma unroll
            for (int nt = 0; nt < 4; nt++) {
                const __half* br = vh + (nt * 8 + g) * VT_STR + k0 + 2 * t;
                uint32_t bb[2] = { ldu32(br), ldu32(br + 8) };
                mma16(acc[nt], a, bb);
            }
        }

#pragma unroll
        for (int nt = 0; nt < 4; nt++) {
            const int d0 = nt * 8 + 2 * t;
#pragma unroll
            for (int e = 0; e < 4; e++) {
                const int rr = r0 + ((e >= 2) ? 8 : 0);
                const int cc = h * 32 + d0 + (e & 1);
                xs[rr * XS_STR + cc] = __float2half_rn(acc[nt][e]);
            }
        }
    }
    __syncthreads();

    // ---- Phase 6: final = o @ proj_w^T + proj_b ----
    {
        const uint4* src = (const uint4*)g_projw_h;
        uint4* dst = (uint4*)wt;
        for (int i = tid; i < 2176; i += THREADS) dst[i] = src[i];
    }
    __syncthreads();
    {
        const int r0 = mi * 16 + g;
        float acc[4][4];
#pragma unroll
        for (int i = 0; i < 4; i++)
#pragma unroll
            for (int j = 0; j < 4; j++) acc[i][j] = 0.f;

#pragma unroll
        for (int ks = 0; ks < 8; ks++) {
            const int k0 = ks * 16;
            const __half* ar = xs + r0 * XS_STR + k0 + 2 * t;
            uint32_t a[4] = { ldu32(ar), ldu32(ar + 8 * XS_STR),
                              ldu32(ar + 8), ldu32(ar + 8 * XS_STR + 8) };
#pragma unroll
            for (int nt = 0; nt < 4; nt++) {
                const __half* br = wt + (nq * 32 + nt * 8 + g) * XS_STR + k0 + 2 * t;
                uint32_t bb[2] = { ldu32(br), ldu32(br + 8) };
                mma16(acc[nt], a, bb);
            }
        }

        // stage fp32 rows [64][132] over q/k region, then coalesced store
        float* os = (float*)(smem + OFF_Q);
#pragma unroll
        for (int nt = 0; nt < 4; nt++) {
            const int c0 = nq * 32 + nt * 8 + 2 * t;
#pragma unroll
            for (int e = 0; e < 4; e++) {
                const int rr = r0 + ((e >= 2) ? 8 : 0);
                const int cc = c0 + (e & 1);
                os[rr * 132 + cc] = acc[nt][e] + sb[384 + cc];
            }
        }
        __syncthreads();

        float4* ob = (float4*)(out + (size_t)b * (NTOK * CDIM));
        for (int i = tid; i < NTOK * 32; i += THREADS) {
            int r = i >> 5, c4 = i & 31;
            const float* p = os + r * 132 + c4 * 4;
            ob[i] = make_float4(p[0], p[1], p[2], p[3]);
        }
    }
}

extern "C" void kernel_launch(void* const* d_in, const int* in_sizes, int n_in,
                              void* d_out, int out_size)
{
    const float* x          = (const float*)d_in[0];
    const float* mask       = (const float*)d_in[1];
    const float* qkv_w      = (const float*)d_in[2];
    const float* qkv_b      = (const float*)d_in[3];
    const float* proj_w     = (const float*)d_in[4];
    const float* proj_b     = (const float*)d_in[5];
    const float* bias_table = (const float*)d_in[6];
    float* out = (float*)d_out;

    const int B = in_sizes[0] / (NTOK * CDIM);   // 8192

    prep_weights<<<(66048 + 255) / 256, 256>>>(qkv_w, qkv_b, proj_w, proj_b);
    prep_bm<<<(64 * 4 * 49 * 56 + 255) / 256, 256>>>(mask, bias_table);

    cudaFuncSetAttribute(window_attn_h,
                         cudaFuncAttributeMaxDynamicSharedMemorySize, SMEM_BYTES);

    window_attn_h<<<B, THREADS, SMEM_BYTES>>>(x, out);
}

// round 8
// speedup vs baseline: 1.3010x; 1.3010x over previous
#include <cuda_runtime.h>
#include <cstdint>

#define NTOK 49
#define CDIM 128
#define NHEAD 4
#define NWIN 64
#define THREADS 512

// ---- persistent prepped buffers (filled by prep kernels each launch) ----
__device__ float g_qkvw[3 * 128 * 132];        // tf32, [j][132] natural k order, q-scale folded
__device__ float g_projw[128 * 132];           // tf32, [j][132]
__device__ float g_qkvb[512];                  // qkv_b (q part scaled) ++ proj_b
__device__ float g_bm[64 * 4 * 49 * 56];       // fused rel-pos-bias + mask, col-padded to 56

// ---- shared memory layout (float offsets) — identical to round 6 ----
#define XS_STR 132
#define XS_OFF 0
#define XS_SZ  (64 * XS_STR)          // 8448
#define R2_OFF (XS_OFF + XS_SZ)       // 8448 : weight tile [128][132] OR attn [4][64][60]
#define R2_SZ  (128 * 132)            // 16896
#define WS_STR 132
#define AT_STR 60
#define AT_HSZ (64 * AT_STR)
#define QKV_OFF (R2_OFF + R2_SZ)      // 25344 : q/k/v [3][4][64][36]
#define QK_STR 36
#define QK_HSZ (64 * QK_STR)
#define QK_CSZ (NHEAD * QK_HSZ)
#define SB_OFF (QKV_OFF + 3 * QK_CSZ) // 52992
#define SMEM_FLOATS (SB_OFF + 512)    // 53504 floats = 214016 bytes

__device__ __forceinline__ float f2tf(float f) {
    uint32_t u;
    asm("cvt.rna.tf32.f32 %0, %1;" : "=r"(u) : "f"(f));
    return __uint_as_float(u);
}
__device__ __forceinline__ uint32_t fau(float f) { return __float_as_uint(f); }

__device__ __forceinline__ void mma8(float c[4], const uint32_t a[4], const uint32_t b[2]) {
    asm volatile(
        "mma.sync.aligned.m16n8k8.row.col.f32.tf32.tf32.f32 "
        "{%0,%1,%2,%3},{%4,%5,%6,%7},{%8,%9},{%0,%1,%2,%3};\n"
        : "+f"(c[0]), "+f"(c[1]), "+f"(c[2]), "+f"(c[3])
        : "r"(a[0]), "r"(a[1]), "r"(a[2]), "r"(a[3]), "r"(b[0]), "r"(b[1]));
}

// ================= prep kernels (once per launch, ~5 us total) =================
__global__ void prep_weights(const float* __restrict__ qkv_w, const float* __restrict__ qkv_b,
                             const float* __restrict__ proj_w, const float* __restrict__ proj_b)
{
    int idx = blockIdx.x * 256 + threadIdx.x;
    const float scale = 0.17677669529663687f;   // 32^-0.5
    if (idx < 49152) {
        int ch = idx >> 14;
        int j  = (idx >> 7) & 127;
        int k  = idx & 127;
        float v = qkv_w[(size_t)(ch * 128 + j) * 128 + k];
        if (ch == 0) v *= scale;
        g_qkvw[ch * 16896 + j * 132 + k] = f2tf(v);
    } else if (idx < 65536) {
        int i2 = idx - 49152;
        int j = i2 >> 7, k = i2 & 127;
        g_projw[j * 132 + k] = f2tf(proj_w[(size_t)j * 128 + k]);
    } else if (idx < 65536 + 384) {
        int i = idx - 65536;
        float v = qkv_b[i];
        if (i < 128) v *= scale;
        g_qkvb[i] = v;
    } else if (idx < 65536 + 512) {
        int i = idx - 65536;
        g_qkvb[i] = proj_b[i - 384];
    }
}

__global__ void prep_bm(const float* __restrict__ mask, const float* __restrict__ bias_table)
{
    int idx = blockIdx.x * 256 + threadIdx.x;
    if (idx >= 64 * 4 * 49 * 56) return;
    int j = idx % 56;
    int rest = idx / 56;
    int i = rest % 49; rest /= 49;
    int h = rest & 3;
    int w = rest >> 2;
    float v = 0.f;
    if (j < 49) {
        int ih = i / 7, iw = i - 7 * ih;
        int jh = j / 7, jw = j - 7 * jh;
        int ridx = (ih - jh + 6) * 13 + (iw - jw + 6);
        v = bias_table[ridx * 4 + h] + mask[(size_t)(w * 49 + i) * 49 + j];
    }
    g_bm[idx] = v;
}

// ================= main kernel =================
__global__ __launch_bounds__(THREADS, 1)
void window_attn_tc(const float* __restrict__ x, float* __restrict__ out)
{
    extern __shared__ float s[];
    float* xs = s + XS_OFF;           // [64][132] tf32: x tile, later attn-out tile
    float* r2 = s + R2_OFF;           // weight tile or attn scores
    float* sb = s + SB_OFF;           // biases

    const int tid  = threadIdx.x;
    const int wid  = tid >> 5;
    const int lane = tid & 31;
    const int g    = lane >> 2;
    const int t    = lane & 3;
    const int b    = blockIdx.x;

    // ---- Phase 1: load x tile (tf32), zero-pad rows 49..63 ; stage biases ----
    {
        const float4* xb = (const float4*)(x + (size_t)b * (NTOK * CDIM));
        for (int i = tid; i < 64 * 32; i += THREADS) {
            int r = i >> 5, c4 = i & 31;
            float4 v = (r < NTOK) ? xb[r * 32 + c4] : make_float4(0.f, 0.f, 0.f, 0.f);
            float* d = xs + r * XS_STR + c4 * 4;
            d[0] = f2tf(v.x); d[1] = f2tf(v.y); d[2] = f2tf(v.z); d[3] = f2tf(v.w);
        }
        sb[tid] = g_qkvb[tid];        // THREADS == 512 == bias count
    }
    __syncthreads();

    // ---- Phase 2: QKV = x @ qkv_w^T + b, 3 chunks; 8 warps x (32x32) tiles ----
    for (int ch = 0; ch < 3; ch++) {
        {
            const float4* src = (const float4*)(g_qkvw + ch * 16896);
            float4* dst = (float4*)r2;
            for (int i = tid; i < 4224; i += THREADS) dst[i] = src[i];
        }
        __syncthreads();

        if (wid < 8) {
            const int mi2 = wid & 1;      // 32-row block
            const int nq  = wid >> 1;     // 32-col block
            const int rA  = mi2 * 32 + g;

            float acc[2][4][4];
#pragma unroll
            for (int u = 0; u < 2; u++)
#pragma unroll
                for (int i = 0; i < 4; i++)
#pragma unroll
                    for (int j = 0; j < 4; j++) acc[u][i][j] = 0.f;

#pragma unroll
            for (int ks = 0; ks < 16; ks++) {
                const int k0 = ks * 8;
                const float* ar0 = xs + rA * XS_STR + k0 + t;
                const float* ar1 = ar0 + 16 * XS_STR;
                uint32_t a0[4] = { fau(ar0[0]), fau(ar0[8 * XS_STR]),
                                   fau(ar0[4]), fau(ar0[8 * XS_STR + 4]) };
                uint32_t a1[4] = { fau(ar1[0]), fau(ar1[8 * XS_STR]),
                                   fau(ar1[4]), fau(ar1[8 * XS_STR + 4]) };
#pragma unroll
                for (int nt = 0; nt < 4; nt++) {
                    const float* br = r2 + (nq * 32 + nt * 8 + g) * WS_STR + k0 + t;
                    uint32_t bb[2] = { fau(br[0]), fau(br[4]) };
                    mma8(acc[0][nt], a0, bb);
                    mma8(acc[1][nt], a1, bb);
                }
            }

            // epilogue -> q/k/v smem (tf32); bias from smem
            float* dst = s + QKV_OFF + ch * QK_CSZ;
            const float* bch = sb + ch * 128;
#pragma unroll
            for (int u = 0; u < 2; u++) {
                const int r0 = rA + u * 16;
#pragma unroll
                for (int nt = 0; nt < 4; nt++) {
                    const int c0 = nq * 32 + nt * 8 + 2 * t;
#pragma unroll
                    for (int e = 0; e < 4; e++) {
                        const int rr = r0 + ((e >= 2) ? 8 : 0);
                        const int cc = c0 + (e & 1);
                        const int h = cc >> 5, dd = cc & 31;
                        dst[h * QK_HSZ + rr * QK_STR + dd] = f2tf(acc[u][nt][e] + bch[cc]);
                    }
                }
            }
        }
        __syncthreads();
    }

    // ---- Phase 3: scores = q k^T + fused(bias+mask) -> attn [4][64][60] ----
    {
        const int h  = wid >> 2;
        const int mi = wid & 3;
        const int r0 = mi * 16 + g;
        const float* qh = s + QKV_OFF + 0 * QK_CSZ + h * QK_HSZ;
        const float* kh = s + QKV_OFF + 1 * QK_CSZ + h * QK_HSZ;

        float acc[7][4];
#pragma unroll
        for (int i = 0; i < 7; i++)
#pragma unroll
            for (int j = 0; j < 4; j++) acc[i][j] = 0.f;

#pragma unroll
        for (int ks = 0; ks < 4; ks++) {
            const int k0 = ks * 8;
            const float* ar = qh + r0 * QK_STR + k0 + t;
            uint32_t a[4] = { fau(ar[0]), fau(ar[8 * QK_STR]),
                              fau(ar[4]), fau(ar[8 * QK_STR + 4]) };
#pragma unroll
            for (int nt = 0; nt < 7; nt++) {
                const float* br = kh + (nt * 8 + g) * QK_STR + k0 + t;
                uint32_t bb[2] = { fau(br[0]), fau(br[4]) };
                mma8(acc[nt], a, bb);
            }
        }

        float* at = r2 + h * AT_HSZ;
        const float* bmw = g_bm + (size_t)(b & (NWIN - 1)) * (4 * 49 * 56) + h * (49 * 56);
        const int rA = r0, rB = r0 + 8;
#pragma unroll
        for (int nt = 0; nt < 7; nt++) {
            const int c0 = nt * 8 + 2 * t;
#pragma unroll
            for (int e = 0; e < 4; e++) {
                const int rr = (e >= 2) ? rB : rA;
                const int jj = c0 + (e & 1);
                float v = 0.f;
                if (rr < NTOK && jj < NTOK)
                    v = acc[nt][e] + __ldg(bmw + rr * 56 + jj);
                at[rr * AT_STR + jj] = v;
            }
        }
    }
    __syncthreads();

    // ---- Phase 4: softmax per (h, i<49) row ----
    if (tid < NHEAD * NTOK) {
        const int h = tid / NTOK;
        const int i = tid - h * NTOK;
        float* row = r2 + h * AT_HSZ + i * AT_STR;
        float m = row[0];
#pragma unroll
        for (int j = 1; j < NTOK; j++) m = fmaxf(m, row[j]);
        float ssum = 0.f;
#pragma unroll
        for (int j = 0; j < NTOK; j++) ssum += __expf(row[j] - m);
        const float inv = 1.0f / ssum;
#pragma unroll
        for (int j = 0; j < NTOK; j++) row[j] = f2tf(__expf(row[j] - m) * inv);
    }
    __syncthreads();

    // ---- Phase 5: o = attn @ v -> xs [64][132] (cols h*32+d), tf32 ----
    {
        const int h  = wid >> 2;
        const int mi = wid & 3;
        const int r0 = mi * 16 + g;
        const float* at = r2 + h * AT_HSZ;
        const float* vh = s + QKV_OFF + 2 * QK_CSZ + h * QK_HSZ;

        float acc[4][4];
#pragma unroll
        for (int i = 0; i < 4; i++)
#pragma unroll
            for (int j = 0; j < 4; j++) acc[i][j] = 0.f;

#pragma unroll
        for (int ks = 0; ks < 7; ks++) {
            const int k0 = ks * 8;
            const float* ar = at + r0 * AT_STR + k0 + t;
            uint32_t a[4] = { fau(ar[0]), fau(ar[8 * AT_STR]),
                              fau(ar[4]), fau(ar[8 * AT_STR + 4]) };
#pragma unroll
            for (int nt = 0; nt < 4; nt++) {
                const float* br = vh + (k0 + t) * QK_STR + nt * 8 + g;
                uint32_t bb[2] = { fau(br[0]), fau(br[4 * QK_STR]) };
                mma8(acc[nt], a, bb);
            }
        }
        __syncthreads();   // attn reads done before r2 is overwritten with proj_w

#pragma unroll
        for (int nt = 0; nt < 4; nt++) {
            const int c0 = nt * 8 + 2 * t;
#pragma unroll
            for (int e = 0; e < 4; e++) {
                const int rr = r0 + ((e >= 2) ? 8 : 0);
                const int dd = c0 + (e & 1);
                xs[rr * XS_STR + h * 32 + dd] = f2tf(acc[nt][e]);
            }
        }
    }
    __syncthreads();

    // ---- Phase 6: final = o @ proj_w^T + proj_b ; 8 warps x (32x32) tiles ----
    {
        const float4* src = (const float4*)g_projw;
        float4* dst = (float4*)r2;
        for (int i = tid; i < 4224; i += THREADS) dst[i] = src[i];
    }
    __syncthreads();
    if (wid < 8) {
        const int mi2 = wid & 1;
        const int nq  = wid >> 1;
        const int rA  = mi2 * 32 + g;

        float acc[2][4][4];
#pragma unroll
        for (int u = 0; u < 2; u++)
#pragma unroll
            for (int i = 0; i < 4; i++)
#pragma unroll
                for (int j = 0; j < 4; j++) acc[u][i][j] = 0.f;

#pragma unroll
        for (int ks = 0; ks < 16; ks++) {
            const int k0 = ks * 8;
            const float* ar0 = xs + rA * XS_STR + k0 + t;
            const float* ar1 = ar0 + 16 * XS_STR;
            uint32_t a0[4] = { fau(ar0[0]), fau(ar0[8 * XS_STR]),
                               fau(ar0[4]), fau(ar0[8 * XS_STR + 4]) };
            uint32_t a1[4] = { fau(ar1[0]), fau(ar1[8 * XS_STR]),
                               fau(ar1[4]), fau(ar1[8 * XS_STR + 4]) };
#pragma unroll
            for (int nt = 0; nt < 4; nt++) {
                const float* br = r2 + (nq * 32 + nt * 8 + g) * WS_STR + k0 + t;
                uint32_t bb[2] = { fau(br[0]), fau(br[4]) };
                mma8(acc[0][nt], a0, bb);
                mma8(acc[1][nt], a1, bb);
            }
        }

        // stage into smem (QKV region, free now) for coalesced global store
        float* os = s + QKV_OFF;      // [64][132]
#pragma unroll
        for (int u = 0; u < 2; u++) {
            const int r0 = rA + u * 16;
#pragma unroll
            for (int nt = 0; nt < 4; nt++) {
                const int c0 = nq * 32 + nt * 8 + 2 * t;
#pragma unroll
                for (int e = 0; e < 4; e++) {
                    const int rr = r0 + ((e >= 2) ? 8 : 0);
                    const int cc = c0 + (e & 1);
                    os[rr * XS_STR + cc] = acc[u][nt][e] + sb[384 + cc];
                }
            }
        }
    }
    __syncthreads();
    {
        float* os = s + QKV_OFF;
        float4* ob = (float4*)(out + (size_t)b * (NTOK * CDIM));
        for (int i = tid; i < NTOK * 32; i += THREADS) {
            int r = i >> 5, c4 = i & 31;
            const float* p = os + r * XS_STR + c4 * 4;
            ob[i] = make_float4(p[0], p[1], p[2], p[3]);
        }
    }
}

extern "C" void kernel_launch(void* const* d_in, const int* in_sizes, int n_in,
                              void* d_out, int out_size)
{
    const float* x          = (const float*)d_in[0];
    const float* mask       = (const float*)d_in[1];
    const float* qkv_w      = (const float*)d_in[2];
    const float* qkv_b      = (const float*)d_in[3];
    const float* proj_w     = (const float*)d_in[4];
    const float* proj_b     = (const float*)d_in[5];
    const float* bias_table = (const float*)d_in[6];
    float* out = (float*)d_out;

    const int B = in_sizes[0] / (NTOK * CDIM);   // 8192
    const int smem_bytes = SMEM_FLOATS * (int)sizeof(float);

    prep_weights<<<(66048 + 255) / 256, 256>>>(qkv_w, qkv_b, proj_w, proj_b);
    prep_bm<<<(64 * 4 * 49 * 56 + 255) / 256, 256>>>(mask, bias_table);

    cudaFuncSetAttribute(window_attn_tc,
                         cudaFuncAttributeMaxDynamicSharedMemorySize, smem_bytes);

    window_attn_tc<<<B, THREADS, smem_bytes>>>(x, out);
}